// round 1
// baseline (speedup 1.0000x reference)
#include <cuda_runtime.h>

// LSTM: B=8192, T=512, I=12, H=20 (PyTorch gate order i,f,g,o), zero init,
// then Linear(H->10) on last hidden state.
//
// Design:
//  - 128 blocks x 320 threads. Block owns 64 consecutive batches = 32 "pairs"
//    (pair p = local batches p and p+32, packed as f32x2 lanes).
//  - warp w (0..9) = unit-group w: handles hidden units {2w, 2w+1} for all 32
//    pairs (lane = pair). Weight loads are warp-uniform (SMEM broadcast).
//  - Per thread per step: 8 gate rows x 32 K -> 256 fma.rn.f32x2.
//  - Weights stored in SMEM pre-duplicated as (w,w) u64 pairs so packed FMA
//    needs no per-use mov.b64 packing.
//  - h double-buffered in SMEM as (b0,b1) f32x2; one __syncthreads per step.
//  - x staged into SMEM every 4 steps, pre-packed as f32x2 pairs.

#define LSTM_H   20
#define LSTM_G   80      // 4*H
#define LSTM_I   12
#define LSTM_KW  32      // I + H
#define LSTM_T   512
#define LSTM_B   8192
#define BPB      64      // batches per block
#define PAIRS    32
#define NWARP    10
#define THREADS  320
#define TCHUNK   4

typedef unsigned long long u64;

__device__ __forceinline__ u64 pack2(float lo, float hi) {
    u64 r; asm("mov.b64 %0, {%1, %2};" : "=l"(r) : "f"(lo), "f"(hi)); return r;
}
__device__ __forceinline__ void unpack2(u64 v, float& lo, float& hi) {
    asm("mov.b64 {%0, %1}, %2;" : "=f"(lo), "=f"(hi) : "l"(v));
}
__device__ __forceinline__ u64 fma2(u64 a, u64 b, u64 c) {
    u64 r; asm("fma.rn.f32x2 %0, %1, %2, %3;" : "=l"(r) : "l"(a), "l"(b), "l"(c));
    return r;
}

__device__ __forceinline__ float sigf(float x) {
    // 1/(1+e^-x); handles large |x| gracefully (inf -> 0).
    return __fdividef(1.0f, 1.0f + __expf(-x));
}
__device__ __forceinline__ float tanh_stable(float x) {
    float ax = fabsf(x);
    float e  = __expf(-2.0f * ax);              // in (0,1], no overflow
    float t  = __fdividef(1.0f - e, 1.0f + e);
    return copysignf(t, x);
}

__global__ void __launch_bounds__(THREADS)
lstm_kernel(const float* __restrict__ x,
            const float* __restrict__ w_ih,
            const float* __restrict__ w_hh,
            const float* __restrict__ b_ih,
            const float* __restrict__ b_hh,
            const float* __restrict__ w_out,
            const float* __restrict__ b_out,
            float* __restrict__ out)
{
    __shared__ __align__(16) u64 wdup[LSTM_G * LSTM_KW]; // 80*32*8 = 20480 B
    __shared__ u64 biasdup[LSTM_G];                      //   640 B
    __shared__ u64 hbuf[2][PAIRS][21];                   // 10752 B (pad 21 for banks)
    __shared__ __align__(16) u64 xs2[PAIRS][50];         // 12800 B (48 used, pad 50)

    const int tid  = threadIdx.x;
    const int lane = tid & 31;     // pair index
    const int wg   = tid >> 5;     // unit-group 0..9 (units 2wg, 2wg+1)
    const int b0   = blockIdx.x * BPB;
    const int u0   = 2 * wg;

    // ---- load weights (duplicated as (w,w)), bias, zero h ----
    for (int i = tid; i < LSTM_G * LSTM_KW; i += THREADS) {
        int g = i >> 5, k = i & 31;
        float w = (k < LSTM_I) ? w_ih[g * LSTM_I + k] : w_hh[g * LSTM_H + (k - LSTM_I)];
        wdup[i] = pack2(w, w);
    }
    for (int i = tid; i < LSTM_G; i += THREADS) {
        float b = b_ih[i] + b_hh[i];
        biasdup[i] = pack2(b, b);
    }
    for (int i = tid; i < PAIRS * 21; i += THREADS) {
        (&hbuf[0][0][0])[i] = 0ull;   // zero hbuf[0]
    }
    __syncthreads();

    // cell state for (unit u, batch-half s): c[u][s]
    float c[2][2] = {{0.f, 0.f}, {0.f, 0.f}};

    const float4* x4 = (const float4*)x;

    #pragma unroll 1
    for (int t = 0; t < LSTM_T; t++) {
        const int tt = t & (TCHUNK - 1);

        if (tt == 0) {
            // stage x[b0..b0+63, t..t+3, :] into xs2 as f32x2 pairs
            // 32 pairs * 12 float4 = 384 float4-pair loads
            #pragma unroll 1
            for (int i = tid; i < PAIRS * (TCHUNK * LSTM_I / 4); i += THREADS) {
                int p = i / 12, q = i - p * 12;
                // float4 index within a batch row: batch stride 1536 float4
                long base = (long)(b0 + p) * 1536 + (long)t * 3 + q;
                float4 fa = x4[base];
                float4 fb = x4[base + 32L * 1536];
                xs2[p][q * 4 + 0] = pack2(fa.x, fb.x);
                xs2[p][q * 4 + 1] = pack2(fa.y, fb.y);
                xs2[p][q * 4 + 2] = pack2(fa.z, fb.z);
                xs2[p][q * 4 + 3] = pack2(fa.w, fb.w);
            }
            __syncthreads();
        }

        const int cur = t & 1, nxt = cur ^ 1;

        // gather xh[0..31]: x (12) then h (20), all packed (b0,b1)
        u64 xh[LSTM_KW];
        {
            const u64* xrow = &xs2[lane][tt * LSTM_I];
            #pragma unroll
            for (int k = 0; k < LSTM_I; k += 2) {
                ulonglong2 v = *(const ulonglong2*)&xrow[k];
                xh[k] = v.x; xh[k + 1] = v.y;
            }
            const u64* hrow = hbuf[cur][lane];
            #pragma unroll
            for (int j = 0; j < LSTM_H; j++) xh[LSTM_I + j] = hrow[j];
        }

        // 8 gate rows: r -> g = (r>>1)*20 + u0 + (r&1)   (i,i,f,f,g,g,o,o)
        u64 acc[8];
        #pragma unroll
        for (int r = 0; r < 8; r++)
            acc[r] = biasdup[(r >> 1) * LSTM_H + u0 + (r & 1)];

        #pragma unroll
        for (int k = 0; k < LSTM_KW; k += 2) {
            #pragma unroll
            for (int r = 0; r < 8; r++) {
                const u64* wrp = &wdup[((r >> 1) * LSTM_H + u0 + (r & 1)) * LSTM_KW];
                ulonglong2 w2 = *(const ulonglong2*)&wrp[k];
                acc[r] = fma2(w2.x, xh[k], acc[r]);
                acc[r] = fma2(w2.y, xh[k + 1], acc[r]);
            }
        }

        // cell update for 2 units x 2 batches
        #pragma unroll
        for (int u = 0; u < 2; u++) {
            float pia, pib, pfa, pfb, pga, pgb, poa, pob;
            unpack2(acc[0 + u], pia, pib);
            unpack2(acc[2 + u], pfa, pfb);
            unpack2(acc[4 + u], pga, pgb);
            unpack2(acc[6 + u], poa, pob);

            float ca = c[u][0], cb = c[u][1];
            ca = sigf(pfa) * ca + sigf(pia) * tanh_stable(pga);
            cb = sigf(pfb) * cb + sigf(pib) * tanh_stable(pgb);
            c[u][0] = ca; c[u][1] = cb;
            float ha = sigf(poa) * tanh_stable(ca);
            float hb = sigf(pob) * tanh_stable(cb);
            hbuf[nxt][lane][u0 + u] = pack2(ha, hb);
        }
        __syncthreads();
    }

    // ---- output Linear: out[b,k] = b_out[k] + sum_j h[b,j] * w_out[k,j] ----
    // final h is in hbuf[0] (last write: t=511 -> nxt = 0)
    #pragma unroll 1
    for (int o = tid; o < BPB * 10; o += THREADS) {
        int bl = o / 10, k = o - bl * 10;
        int p = bl & 31;
        bool hi = (bl >= 32);
        float sum = b_out[k];
        #pragma unroll
        for (int j = 0; j < LSTM_H; j++) {
            float ha, hb; unpack2(hbuf[0][p][j], ha, hb);
            sum = fmaf(hi ? hb : ha, w_out[k * LSTM_H + j], sum);
        }
        out[(long)(b0 + bl) * 10 + k] = sum;
    }
}

extern "C" void kernel_launch(void* const* d_in, const int* in_sizes, int n_in,
                              void* d_out, int out_size)
{
    const float* x     = (const float*)d_in[0];
    const float* w_ih  = (const float*)d_in[1];
    const float* w_hh  = (const float*)d_in[2];
    const float* b_ih  = (const float*)d_in[3];
    const float* b_hh  = (const float*)d_in[4];
    const float* w_out = (const float*)d_in[5];
    const float* b_out = (const float*)d_in[6];
    float* out = (float*)d_out;

    lstm_kernel<<<LSTM_B / BPB, THREADS>>>(x, w_ih, w_hh, b_ih, b_hh, w_out, b_out, out);
}

// round 2
// speedup vs baseline: 1.2727x; 1.2727x over previous
#include <cuda_runtime.h>

// LSTM: B=8192, T=512, I=12, H=20 (gate order i,f,g,o), zero init,
// then Linear(H->10) on last hidden state.
//
// Mapping (Q=4, R=4):
//  - 128 blocks x 320 threads (10 warps). Block owns 64 batches = 32 pairs,
//    pair p = (b0+p, b0+p+32) packed in f32x2 lanes.
//  - Warp wg covers units {2wg, 2wg+1}: lanes 0-15 = unit 2wg, lanes 16-31 =
//    unit 2wg+1. Lane's pair-slot s = lane&15; thread handles pairs s and s+16.
//  - Per thread/step: 4 gate rows x 2 pairs x 32 K -> 256 fma.rn.f32x2,
//    64 weight LDS.128 (1 wf each, dual half-warp addr, padded stride 34),
//    64 xh LDS.64 (each = 16 consecutive u64 broadcast -> 1 wf).
//  - hbuf / xs staged value-major [val][pair] -> conflict-free.
//  - tanh.approx.f32 epilogue.

#define LSTM_H   20
#define LSTM_G   80
#define LSTM_I   12
#define LSTM_T   512
#define LSTM_B   8192
#define BPB      64
#define PAIRS    32
#define THREADS  320
#define TCHUNK   4
#define WSTR     34      // wdup row stride in u64 (padded: 272B, offsets halves by 16B bank-wise)

typedef unsigned long long u64;

__device__ __forceinline__ u64 pack2(float lo, float hi) {
    u64 r; asm("mov.b64 %0, {%1, %2};" : "=l"(r) : "f"(lo), "f"(hi)); return r;
}
__device__ __forceinline__ void unpack2(u64 v, float& lo, float& hi) {
    asm("mov.b64 {%0, %1}, %2;" : "=f"(lo), "=f"(hi) : "l"(v));
}
__device__ __forceinline__ u64 fma2(u64 a, u64 b, u64 c) {
    u64 r; asm("fma.rn.f32x2 %0, %1, %2, %3;" : "=l"(r) : "l"(a), "l"(b), "l"(c));
    return r;
}
__device__ __forceinline__ float tanhA(float x) {
    float y; asm("tanh.approx.f32 %0, %1;" : "=f"(y) : "f"(x)); return y;
}
__device__ __forceinline__ float sigA(float x) {
    return fmaf(tanhA(0.5f * x), 0.5f, 0.5f);
}

__global__ void __launch_bounds__(THREADS, 1)
lstm_kernel(const float* __restrict__ x,
            const float* __restrict__ w_ih,
            const float* __restrict__ w_hh,
            const float* __restrict__ b_ih,
            const float* __restrict__ b_hh,
            const float* __restrict__ w_out,
            const float* __restrict__ b_out,
            float* __restrict__ out)
{
    __shared__ __align__(16) u64 wdup[LSTM_G * WSTR];        // 21760 B
    __shared__ __align__(16) u64 hbuf[2][LSTM_H][PAIRS];     // 10240 B
    __shared__ __align__(16) u64 xs2[TCHUNK * LSTM_I][PAIRS];// 12288 B

    const int tid  = threadIdx.x;
    const int lane = tid & 31;
    const int wg   = tid >> 5;         // 0..9
    const int half = lane >> 4;        // 0/1
    const int slot = lane & 15;        // pair-slot; thread handles pairs slot, slot+16
    const int u    = 2 * wg + half;    // unit 0..19
    const int b0   = blockIdx.x * BPB;

    // ---- stage weights as (w,w) pairs, padded rows ----
    for (int i = tid; i < LSTM_G * 32; i += THREADS) {
        int g = i >> 5, k = i & 31;
        float w = (k < LSTM_I) ? w_ih[g * LSTM_I + k] : w_hh[g * LSTM_H + (k - LSTM_I)];
        wdup[g * WSTR + k] = pack2(w, w);
    }
    for (int i = tid; i < LSTM_H * PAIRS; i += THREADS)
        (&hbuf[0][0][0])[i] = 0ull;
    __syncthreads();

    // bias in registers (this thread's 4 gate rows)
    u64 bias[4];
    #pragma unroll
    for (int q = 0; q < 4; q++) {
        float b = b_ih[q * LSTM_H + u] + b_hh[q * LSTM_H + u];
        bias[q] = pack2(b, b);
    }

    // weight row pointers (hoisted)
    const u64* wr0 = &wdup[(0 * LSTM_H + u) * WSTR];
    const u64* wr1 = &wdup[(1 * LSTM_H + u) * WSTR];
    const u64* wr2 = &wdup[(2 * LSTM_H + u) * WSTR];
    const u64* wr3 = &wdup[(3 * LSTM_H + u) * WSTR];

    // cell state: pair A = slot, pair B = slot+16; each (lo,hi) batches
    float cA0 = 0.f, cA1 = 0.f, cB0 = 0.f, cB1 = 0.f;

    const float4* x4 = (const float4*)x;

    #pragma unroll 1
    for (int t = 0; t < LSTM_T; t++) {
        const int tt = t & (TCHUNK - 1);

        if (tt == 0) {
            // stage x[b0..b0+63, t..t+3, :] -> xs2 value-major
            #pragma unroll 1
            for (int i = tid; i < PAIRS * LSTM_I; i += THREADS) {
                int p = i / 12, q4 = i - p * 12;
                long base = (long)(b0 + p) * 1536 + (long)t * 3 + q4;
                float4 fa = x4[base];
                float4 fb = x4[base + 32L * 1536];
                xs2[4 * q4 + 0][p] = pack2(fa.x, fb.x);
                xs2[4 * q4 + 1][p] = pack2(fa.y, fb.y);
                xs2[4 * q4 + 2][p] = pack2(fa.z, fb.z);
                xs2[4 * q4 + 3][p] = pack2(fa.w, fb.w);
            }
            __syncthreads();
        }

        const int cur = t & 1, nxt = cur ^ 1;

        u64 aA0 = bias[0], aA1 = bias[1], aA2 = bias[2], aA3 = bias[3];
        u64 aB0 = bias[0], aB1 = bias[1], aB2 = bias[2], aB3 = bias[3];

        // ---- x part: k = 0..11 ----
        const u64* xcol = &xs2[tt * LSTM_I][0];
        #pragma unroll
        for (int k = 0; k < LSTM_I; k += 2) {
            ulonglong2 w0 = *(const ulonglong2*)(wr0 + k);
            ulonglong2 w1 = *(const ulonglong2*)(wr1 + k);
            ulonglong2 w2 = *(const ulonglong2*)(wr2 + k);
            ulonglong2 w3 = *(const ulonglong2*)(wr3 + k);
            u64 xA0 = xcol[k * PAIRS + slot];
            u64 xA1 = xcol[(k + 1) * PAIRS + slot];
            u64 xB0 = xcol[k * PAIRS + slot + 16];
            u64 xB1 = xcol[(k + 1) * PAIRS + slot + 16];
            aA0 = fma2(w0.x, xA0, aA0); aA0 = fma2(w0.y, xA1, aA0);
            aA1 = fma2(w1.x, xA0, aA1); aA1 = fma2(w1.y, xA1, aA1);
            aA2 = fma2(w2.x, xA0, aA2); aA2 = fma2(w2.y, xA1, aA2);
            aA3 = fma2(w3.x, xA0, aA3); aA3 = fma2(w3.y, xA1, aA3);
            aB0 = fma2(w0.x, xB0, aB0); aB0 = fma2(w0.y, xB1, aB0);
            aB1 = fma2(w1.x, xB0, aB1); aB1 = fma2(w1.y, xB1, aB1);
            aB2 = fma2(w2.x, xB0, aB2); aB2 = fma2(w2.y, xB1, aB2);
            aB3 = fma2(w3.x, xB0, aB3); aB3 = fma2(w3.y, xB1, aB3);
        }

        // ---- h part: k = 0..19 (weight offset +12) ----
        const u64* hc = &hbuf[cur][0][0];
        #pragma unroll
        for (int k = 0; k < LSTM_H; k += 2) {
            ulonglong2 w0 = *(const ulonglong2*)(wr0 + LSTM_I + k);
            ulonglong2 w1 = *(const ulonglong2*)(wr1 + LSTM_I + k);
            ulonglong2 w2 = *(const ulonglong2*)(wr2 + LSTM_I + k);
            ulonglong2 w3 = *(const ulonglong2*)(wr3 + LSTM_I + k);
            u64 hA0 = hc[k * PAIRS + slot];
            u64 hA1 = hc[(k + 1) * PAIRS + slot];
            u64 hB0 = hc[k * PAIRS + slot + 16];
            u64 hB1 = hc[(k + 1) * PAIRS + slot + 16];
            aA0 = fma2(w0.x, hA0, aA0); aA0 = fma2(w0.y, hA1, aA0);
            aA1 = fma2(w1.x, hA0, aA1); aA1 = fma2(w1.y, hA1, aA1);
            aA2 = fma2(w2.x, hA0, aA2); aA2 = fma2(w2.y, hA1, aA2);
            aA3 = fma2(w3.x, hA0, aA3); aA3 = fma2(w3.y, hA1, aA3);
            aB0 = fma2(w0.x, hB0, aB0); aB0 = fma2(w0.y, hB1, aB0);
            aB1 = fma2(w1.x, hB0, aB1); aB1 = fma2(w1.y, hB1, aB1);
            aB2 = fma2(w2.x, hB0, aB2); aB2 = fma2(w2.y, hB1, aB2);
            aB3 = fma2(w3.x, hB0, aB3); aB3 = fma2(w3.y, hB1, aB3);
        }

        // ---- cell update, pair A ----
        {
            float i0, i1, f0, f1, g0, g1, o0, o1;
            unpack2(aA0, i0, i1); unpack2(aA1, f0, f1);
            unpack2(aA2, g0, g1); unpack2(aA3, o0, o1);
            cA0 = sigA(f0) * cA0 + sigA(i0) * tanhA(g0);
            cA1 = sigA(f1) * cA1 + sigA(i1) * tanhA(g1);
            float h0 = sigA(o0) * tanhA(cA0);
            float h1 = sigA(o1) * tanhA(cA1);
            hbuf[nxt][u][slot] = pack2(h0, h1);
        }
        // ---- cell update, pair B ----
        {
            float i0, i1, f0, f1, g0, g1, o0, o1;
            unpack2(aB0, i0, i1); unpack2(aB1, f0, f1);
            unpack2(aB2, g0, g1); unpack2(aB3, o0, o1);
            cB0 = sigA(f0) * cB0 + sigA(i0) * tanhA(g0);
            cB1 = sigA(f1) * cB1 + sigA(i1) * tanhA(g1);
            float h0 = sigA(o0) * tanhA(cB0);
            float h1 = sigA(o1) * tanhA(cB1);
            hbuf[nxt][u][slot + 16] = pack2(h0, h1);
        }
        __syncthreads();
    }

    // ---- output Linear (final h is in hbuf[0]: t=511 -> nxt=0) ----
    #pragma unroll 1
    for (int o = tid; o < BPB * 10; o += THREADS) {
        int bl = o / 10, k = o - bl * 10;
        int p = bl & 31;
        bool hi = (bl >= 32);
        float sum = b_out[k];
        #pragma unroll
        for (int j = 0; j < LSTM_H; j++) {
            float ha, hb; unpack2(hbuf[0][j][p], ha, hb);
            sum = fmaf(hi ? hb : ha, w_out[k * LSTM_H + j], sum);
        }
        out[(long)(b0 + bl) * 10 + k] = sum;
    }
}

extern "C" void kernel_launch(void* const* d_in, const int* in_sizes, int n_in,
                              void* d_out, int out_size)
{
    const float* x     = (const float*)d_in[0];
    const float* w_ih  = (const float*)d_in[1];
    const float* w_hh  = (const float*)d_in[2];
    const float* b_ih  = (const float*)d_in[3];
    const float* b_hh  = (const float*)d_in[4];
    const float* w_out = (const float*)d_in[5];
    const float* b_out = (const float*)d_in[6];
    float* out = (float*)d_out;

    lstm_kernel<<<LSTM_B / BPB, THREADS>>>(x, w_ih, w_hh, b_ih, b_hh, w_out, b_out, out);
}

// round 3
// speedup vs baseline: 1.3195x; 1.0367x over previous
#include <cuda_runtime.h>

// LSTM B=8192, T=512, I=12, H=20 (i,f,g,o), zero init; Linear(H->10) on h_T.
//
// Mapping (Q=1, R=4): thread = (1 pair of batches packed f32x2) x (1 unit, 4 gate rows).
//  - Block: 160 threads (5 warps), BPB=16 batches = 8 pairs. Grid = 512 (fills 148 SMs).
//  - Warp wg: units 4wg..4wg+3 (lane>>3) x slots 0..7 (lane&7).
//  - Per thread/step: 128 fma.rn.f32x2, 64 weight LDS.128 (1 wf: 4x16B groups),
//    16 xh LDS.128 (1 wf: 8 slots x 16B), ~32 epilogue.
//  - SMEM slot-major with pad so strides = 16 mod 128 B -> conflict-free LDS.128.
//  - x prefetched to registers one chunk (4 steps) ahead; double-buffered SMEM.

#define LSTM_H   20
#define LSTM_G   80
#define LSTM_I   12
#define LSTM_T   512
#define BPB      16
#define NPAIR    8
#define THREADS  160
#define GRID     512
#define WSTR     34      // weight row stride (u64): 272B == 16 mod 128
#define HSTR     26      // h slot stride (u64):   208B == 80 mod 128 (16B-grid distinct)
#define XSTR     50      // x slot stride (u64):   400B == 16 mod 128

typedef unsigned long long u64;

__device__ __forceinline__ u64 pack2(float lo, float hi) {
    u64 r; asm("mov.b64 %0, {%1, %2};" : "=l"(r) : "f"(lo), "f"(hi)); return r;
}
__device__ __forceinline__ void unpack2(u64 v, float& lo, float& hi) {
    asm("mov.b64 {%0, %1}, %2;" : "=f"(lo), "=f"(hi) : "l"(v));
}
__device__ __forceinline__ u64 fma2(u64 a, u64 b, u64 c) {
    u64 r; asm("fma.rn.f32x2 %0, %1, %2, %3;" : "=l"(r) : "l"(a), "l"(b), "l"(c));
    return r;
}
__device__ __forceinline__ float tanhA(float x) {
    float y; asm("tanh.approx.f32 %0, %1;" : "=f"(y) : "f"(x)); return y;
}
__device__ __forceinline__ float sigA(float x) {
    return fmaf(tanhA(0.5f * x), 0.5f, 0.5f);
}

__global__ void __launch_bounds__(THREADS)
lstm_kernel(const float* __restrict__ x,
            const float* __restrict__ w_ih,
            const float* __restrict__ w_hh,
            const float* __restrict__ b_ih,
            const float* __restrict__ b_hh,
            const float* __restrict__ w_out,
            const float* __restrict__ b_out,
            float* __restrict__ out)
{
    __shared__ __align__(16) u64 wdup[LSTM_G * WSTR];   // 21760 B
    __shared__ __align__(16) u64 hbuf[2][NPAIR * HSTR]; //  3328 B
    __shared__ __align__(16) u64 xs2[2][NPAIR * XSTR];  //  6400 B

    const int tid  = threadIdx.x;
    const int lane = tid & 31;
    const int wg   = tid >> 5;            // 0..4
    const int slot = lane & 7;            // pair slot 0..7
    const int usub = lane >> 3;           // 0..3
    const int u    = 4 * wg + usub;       // unit 0..19
    const int b0   = blockIdx.x * BPB;

    // ---- stage duplicated weights ----
    for (int i = tid; i < LSTM_G * 32; i += THREADS) {
        int g = i >> 5, k = i & 31;
        float w = (k < LSTM_I) ? w_ih[g * LSTM_I + k] : w_hh[g * LSTM_H + (k - LSTM_I)];
        wdup[g * WSTR + k] = pack2(w, w);
    }
    for (int i = tid; i < NPAIR * HSTR; i += THREADS) hbuf[0][i] = 0ull;

    // bias in regs (4 gate rows of this unit)
    u64 bias[4];
    #pragma unroll
    for (int q = 0; q < 4; q++) {
        float b = b_ih[q * LSTM_H + u] + b_hh[q * LSTM_H + u];
        bias[q] = pack2(b, b);
    }

    const u64* wr0 = &wdup[(0 * LSTM_H + u) * WSTR];
    const u64* wr1 = &wdup[(1 * LSTM_H + u) * WSTR];
    const u64* wr2 = &wdup[(2 * LSTM_H + u) * WSTR];
    const u64* wr3 = &wdup[(3 * LSTM_H + u) * WSTR];

    // ---- x prefetch machinery: 96 loader threads, 1 float4-pair each per chunk ----
    const float4* x4 = (const float4*)x;
    const int  pch  = tid / 12;
    const int  qch  = tid - pch * 12;
    const bool ldr  = (tid < 96);
    float4 fa, fb;

    // chunk 0 -> regs -> buf 0; start chunk 1 loads
    if (ldr) {
        long base = (long)(b0 + pch) * 1536 + qch;
        fa = x4[base]; fb = x4[base + 8L * 1536];
        u64* d = &xs2[0][pch * XSTR + 4 * qch];
        d[0] = pack2(fa.x, fb.x); d[1] = pack2(fa.y, fb.y);
        d[2] = pack2(fa.z, fb.z); d[3] = pack2(fa.w, fb.w);
        base += 12;  // t = 4
        fa = x4[base]; fb = x4[base + 8L * 1536];
    }
    __syncthreads();

    float c0 = 0.f, c1 = 0.f;

    #pragma unroll 1
    for (int t = 0; t < LSTM_T; t++) {
        const int tt = t & 3;
        if (tt == 0 && t > 0) {
            const int cbuf = (t >> 2) & 1;
            if (ldr) {
                u64* d = &xs2[cbuf][pch * XSTR + 4 * qch];
                d[0] = pack2(fa.x, fb.x); d[1] = pack2(fa.y, fb.y);
                d[2] = pack2(fa.z, fb.z); d[3] = pack2(fa.w, fb.w);
                if (t + 4 < LSTM_T) {
                    long base = (long)(b0 + pch) * 1536 + (long)(t + 4) * 3 + qch;
                    fa = x4[base]; fb = x4[base + 8L * 1536];
                }
            }
            __syncthreads();
        }

        const int cur = t & 1, nxt = cur ^ 1;

        u64 aI = bias[0], aF = bias[1], aG = bias[2], aO = bias[3];

        // ---- x part: k = 0..11 ----
        const u64* xrow = &xs2[(t >> 2) & 1][slot * XSTR + tt * LSTM_I];
        #pragma unroll
        for (int k = 0; k < LSTM_I; k += 2) {
            ulonglong2 xv = *(const ulonglong2*)(xrow + k);
            ulonglong2 w0 = *(const ulonglong2*)(wr0 + k);
            ulonglong2 w1 = *(const ulonglong2*)(wr1 + k);
            ulonglong2 w2 = *(const ulonglong2*)(wr2 + k);
            ulonglong2 w3 = *(const ulonglong2*)(wr3 + k);
            aI = fma2(w0.x, xv.x, aI); aI = fma2(w0.y, xv.y, aI);
            aF = fma2(w1.x, xv.x, aF); aF = fma2(w1.y, xv.y, aF);
            aG = fma2(w2.x, xv.x, aG); aG = fma2(w2.y, xv.y, aG);
            aO = fma2(w3.x, xv.x, aO); aO = fma2(w3.y, xv.y, aO);
        }

        // ---- h part: k = 0..19 ----
        const u64* hrow = &hbuf[cur][slot * HSTR];
        #pragma unroll
        for (int k = 0; k < LSTM_H; k += 2) {
            ulonglong2 hv = *(const ulonglong2*)(hrow + k);
            ulonglong2 w0 = *(const ulonglong2*)(wr0 + LSTM_I + k);
            ulonglong2 w1 = *(const ulonglong2*)(wr1 + LSTM_I + k);
            ulonglong2 w2 = *(const ulonglong2*)(wr2 + LSTM_I + k);
            ulonglong2 w3 = *(const ulonglong2*)(wr3 + LSTM_I + k);
            aI = fma2(w0.x, hv.x, aI); aI = fma2(w0.y, hv.y, aI);
            aF = fma2(w1.x, hv.x, aF); aF = fma2(w1.y, hv.y, aF);
            aG = fma2(w2.x, hv.x, aG); aG = fma2(w2.y, hv.y, aG);
            aO = fma2(w3.x, hv.x, aO); aO = fma2(w3.y, hv.y, aO);
        }

        // ---- cell update (1 unit, 2 batches) ----
        {
            float i0, i1, f0, f1, g0, g1, o0, o1;
            unpack2(aI, i0, i1); unpack2(aF, f0, f1);
            unpack2(aG, g0, g1); unpack2(aO, o0, o1);
            c0 = sigA(f0) * c0 + sigA(i0) * tanhA(g0);
            c1 = sigA(f1) * c1 + sigA(i1) * tanhA(g1);
            float h0 = sigA(o0) * tanhA(c0);
            float h1 = sigA(o1) * tanhA(c1);
            hbuf[nxt][slot * HSTR + u] = pack2(h0, h1);
        }
        __syncthreads();
    }

    // ---- output Linear (final h in hbuf[0]: t=511 -> nxt=0) ----
    {
        int bl = tid / 10, k = tid - bl * 10;   // bl 0..15, k 0..9
        if (bl < BPB) {
            int p  = bl & 7;
            bool hi = (bl >= 8);
            float sum = b_out[k];
            #pragma unroll
            for (int j = 0; j < LSTM_H; j++) {
                float ha, hb; unpack2(hbuf[0][p * HSTR + j], ha, hb);
                sum = fmaf(hi ? hb : ha, w_out[k * LSTM_H + j], sum);
            }
            out[(long)(b0 + p + (hi ? 8 : 0)) * 10 + k] = sum;
        }
    }
}

extern "C" void kernel_launch(void* const* d_in, const int* in_sizes, int n_in,
                              void* d_out, int out_size)
{
    const float* x     = (const float*)d_in[0];
    const float* w_ih  = (const float*)d_in[1];
    const float* w_hh  = (const float*)d_in[2];
    const float* b_ih  = (const float*)d_in[3];
    const float* b_hh  = (const float*)d_in[4];
    const float* w_out = (const float*)d_in[5];
    const float* b_out = (const float*)d_in[6];
    float* out = (float*)d_out;

    lstm_kernel<<<GRID, THREADS>>>(x, w_ih, w_hh, b_ih, b_hh, w_out, b_out, out);
}

// round 4
// speedup vs baseline: 1.8315x; 1.3881x over previous
#include <cuda_runtime.h>

// LSTM B=8192, T=512, I=12, H=20 (i,f,g,o), zero init; Linear(H->10) on h_T.
//
// k-vectorized f32x2: fma2((w_k,w_k1),(x_k,x_k1),acc) accumulates 2 partial sums
// per gate, horizontal-added once per step. No operand duplication: weights and
// activations both live in SMEM in natural contiguous layout.
//
//  - Block: 160 threads (5 warps), BPB = 16 batches, grid = 512.
//  - Warp wg: lane = usub*8+g -> unit u = 4*wg+usub, batches g and g+8.
//  - Thread/step: 128 fma2, 18+30 = 48 LDS.128 (all 1-wavefront layouts), epilogue.
//  - Strides: w_ih rows 12 fl (48B), w_hh/h rows 20 fl (80B), x rows 52 fl (208B)
//    -> all warp footprints conflict-free (distinct 16B banks).

#define LSTM_H   20
#define LSTM_I   12
#define LSTM_T   512
#define BPB      16
#define THREADS  160
#define GRID     512
#define XROW     52

typedef unsigned long long u64;

__device__ __forceinline__ u64 pack2(float lo, float hi) {
    u64 r; asm("mov.b64 %0, {%1, %2};" : "=l"(r) : "f"(lo), "f"(hi)); return r;
}
__device__ __forceinline__ void unpack2(u64 v, float& lo, float& hi) {
    asm("mov.b64 {%0, %1}, %2;" : "=f"(lo), "=f"(hi) : "l"(v));
}
__device__ __forceinline__ u64 fma2(u64 a, u64 b, u64 c) {
    u64 r; asm("fma.rn.f32x2 %0, %1, %2, %3;" : "=l"(r) : "l"(a), "l"(b), "l"(c));
    return r;
}
__device__ __forceinline__ float tanhA(float x) {
    float y; asm("tanh.approx.f32 %0, %1;" : "=f"(y) : "f"(x)); return y;
}
__device__ __forceinline__ float sigA(float x) {
    return fmaf(tanhA(0.5f * x), 0.5f, 0.5f);
}

__global__ void __launch_bounds__(THREADS)
lstm_kernel(const float* __restrict__ x,
            const float* __restrict__ w_ih,
            const float* __restrict__ w_hh,
            const float* __restrict__ b_ih,
            const float* __restrict__ b_hh,
            const float* __restrict__ w_out,
            const float* __restrict__ b_out,
            float* __restrict__ out)
{
    __shared__ __align__(16) float wih_s[80 * LSTM_I];        // 3840 B, stride 12
    __shared__ __align__(16) float whh_s[80 * LSTM_H];        // 6400 B, stride 20
    __shared__ __align__(16) float hbuf[2][BPB * LSTM_H];     // 2560 B, stride 20
    __shared__ __align__(16) float xs[2][BPB * XROW];         // 6656 B, stride 52

    const int tid  = threadIdx.x;
    const int lane = tid & 31;
    const int wg   = tid >> 5;          // 0..4
    const int usub = lane >> 3;         // 0..3
    const int g    = lane & 7;          // batch group
    const int u    = 4 * wg + usub;     // unit 0..19
    const int bA   = g, bB = g + 8;
    const int b0   = blockIdx.x * BPB;

    // ---- stage weights (verbatim row-major copies) ----
    for (int i = tid; i < 80 * LSTM_I; i += THREADS) wih_s[i] = w_ih[i];
    for (int i = tid; i < 80 * LSTM_H; i += THREADS) whh_s[i] = w_hh[i];
    for (int i = tid; i < BPB * LSTM_H; i += THREADS) hbuf[0][i] = 0.f;

    // bias packed as (b, 0) -> folded into acc init
    const u64 bI = pack2(b_ih[0 * LSTM_H + u] + b_hh[0 * LSTM_H + u], 0.f);
    const u64 bF = pack2(b_ih[1 * LSTM_H + u] + b_hh[1 * LSTM_H + u], 0.f);
    const u64 bG = pack2(b_ih[2 * LSTM_H + u] + b_hh[2 * LSTM_H + u], 0.f);
    const u64 bO = pack2(b_ih[3 * LSTM_H + u] + b_hh[3 * LSTM_H + u], 0.f);

    const u64* wi0 = (const u64*)&wih_s[(0 * LSTM_H + u) * LSTM_I];
    const u64* wi1 = (const u64*)&wih_s[(1 * LSTM_H + u) * LSTM_I];
    const u64* wi2 = (const u64*)&wih_s[(2 * LSTM_H + u) * LSTM_I];
    const u64* wi3 = (const u64*)&wih_s[(3 * LSTM_H + u) * LSTM_I];
    const u64* wh0 = (const u64*)&whh_s[(0 * LSTM_H + u) * LSTM_H];
    const u64* wh1 = (const u64*)&whh_s[(1 * LSTM_H + u) * LSTM_H];
    const u64* wh2 = (const u64*)&whh_s[(2 * LSTM_H + u) * LSTM_H];
    const u64* wh3 = (const u64*)&whh_s[(3 * LSTM_H + u) * LSTM_H];

    // ---- x prefetch: 192 float4 items per 4-step chunk, 160 threads ----
    const float4* x4 = (const float4*)x;
    const int i0 = tid, i1 = tid + THREADS;
    const int pb0 = i0 / 12, pq0 = i0 - pb0 * 12;
    const int pb1 = i1 / 12, pq1 = i1 - pb1 * 12;
    const bool has1 = (i1 < BPB * 12);
    const long gbase0 = (long)(b0 + pb0) * 1536 + pq0;
    const long gbase1 = (long)(b0 + pb1) * 1536 + pq1;
    float4 pf0, pf1;

    // chunk 0 -> buf 0 directly; prefetch chunk 1
    {
        float4 v = x4[gbase0];
        *(float4*)&xs[0][pb0 * XROW + 4 * pq0] = v;
        if (has1) {
            float4 v1 = x4[gbase1];
            *(float4*)&xs[0][pb1 * XROW + 4 * pq1] = v1;
        }
        pf0 = x4[gbase0 + 12];
        if (has1) pf1 = x4[gbase1 + 12];
    }
    __syncthreads();

    float cA = 0.f, cB = 0.f;

    #pragma unroll 1
    for (int t = 0; t < LSTM_T; t++) {
        const int tt = t & 3;
        if (tt == 0 && t > 0) {
            const int buf = (t >> 2) & 1;
            *(float4*)&xs[buf][pb0 * XROW + 4 * pq0] = pf0;
            if (has1) *(float4*)&xs[buf][pb1 * XROW + 4 * pq1] = pf1;
            if (t + 4 < LSTM_T) {
                pf0 = x4[gbase0 + (long)(t + 4) * 3];
                if (has1) pf1 = x4[gbase1 + (long)(t + 4) * 3];
            }
            __syncthreads();
        }

        const int cur = t & 1, nxt = cur ^ 1;

        u64 aA0 = bI, aA1 = bF, aA2 = bG, aA3 = bO;
        u64 aB0 = bI, aB1 = bF, aB2 = bG, aB3 = bO;

        // ---- x part: 12 floats = 6 u64 ----
        {
            const u64* xrA = (const u64*)&xs[(t >> 2) & 1][bA * XROW + tt * LSTM_I];
            const u64* xrB = (const u64*)&xs[(t >> 2) & 1][bB * XROW + tt * LSTM_I];
            #pragma unroll
            for (int k = 0; k < 6; k += 2) {
                ulonglong2 xA = *(const ulonglong2*)(xrA + k);
                ulonglong2 xB = *(const ulonglong2*)(xrB + k);
                ulonglong2 w0 = *(const ulonglong2*)(wi0 + k);
                ulonglong2 w1 = *(const ulonglong2*)(wi1 + k);
                ulonglong2 w2 = *(const ulonglong2*)(wi2 + k);
                ulonglong2 w3 = *(const ulonglong2*)(wi3 + k);
                aA0 = fma2(w0.x, xA.x, aA0); aA0 = fma2(w0.y, xA.y, aA0);
                aA1 = fma2(w1.x, xA.x, aA1); aA1 = fma2(w1.y, xA.y, aA1);
                aA2 = fma2(w2.x, xA.x, aA2); aA2 = fma2(w2.y, xA.y, aA2);
                aA3 = fma2(w3.x, xA.x, aA3); aA3 = fma2(w3.y, xA.y, aA3);
                aB0 = fma2(w0.x, xB.x, aB0); aB0 = fma2(w0.y, xB.y, aB0);
                aB1 = fma2(w1.x, xB.x, aB1); aB1 = fma2(w1.y, xB.y, aB1);
                aB2 = fma2(w2.x, xB.x, aB2); aB2 = fma2(w2.y, xB.y, aB2);
                aB3 = fma2(w3.x, xB.x, aB3); aB3 = fma2(w3.y, xB.y, aB3);
            }
        }

        // ---- h part: 20 floats = 10 u64 ----
        {
            const u64* hrA = (const u64*)&hbuf[cur][bA * LSTM_H];
            const u64* hrB = (const u64*)&hbuf[cur][bB * LSTM_H];
            #pragma unroll
            for (int k = 0; k < 10; k += 2) {
                ulonglong2 hA = *(const ulonglong2*)(hrA + k);
                ulonglong2 hB = *(const ulonglong2*)(hrB + k);
                ulonglong2 w0 = *(const ulonglong2*)(wh0 + k);
                ulonglong2 w1 = *(const ulonglong2*)(wh1 + k);
                ulonglong2 w2 = *(const ulonglong2*)(wh2 + k);
                ulonglong2 w3 = *(const ulonglong2*)(wh3 + k);
                aA0 = fma2(w0.x, hA.x, aA0); aA0 = fma2(w0.y, hA.y, aA0);
                aA1 = fma2(w1.x, hA.x, aA1); aA1 = fma2(w1.y, hA.y, aA1);
                aA2 = fma2(w2.x, hA.x, aA2); aA2 = fma2(w2.y, hA.y, aA2);
                aA3 = fma2(w3.x, hA.x, aA3); aA3 = fma2(w3.y, hA.y, aA3);
                aB0 = fma2(w0.x, hB.x, aB0); aB0 = fma2(w0.y, hB.y, aB0);
                aB1 = fma2(w1.x, hB.x, aB1); aB1 = fma2(w1.y, hB.y, aB1);
                aB2 = fma2(w2.x, hB.x, aB2); aB2 = fma2(w2.y, hB.y, aB2);
                aB3 = fma2(w3.x, hB.x, aB3); aB3 = fma2(w3.y, hB.y, aB3);
            }
        }

        // ---- horizontal add + cell update ----
        {
            float lo, hi;
            unpack2(aA0, lo, hi); float gi = lo + hi;
            unpack2(aA1, lo, hi); float gf = lo + hi;
            unpack2(aA2, lo, hi); float gg = lo + hi;
            unpack2(aA3, lo, hi); float go = lo + hi;
            cA = sigA(gf) * cA + sigA(gi) * tanhA(gg);
            hbuf[nxt][bA * LSTM_H + u] = sigA(go) * tanhA(cA);
        }
        {
            float lo, hi;
            unpack2(aB0, lo, hi); float gi = lo + hi;
            unpack2(aB1, lo, hi); float gf = lo + hi;
            unpack2(aB2, lo, hi); float gg = lo + hi;
            unpack2(aB3, lo, hi); float go = lo + hi;
            cB = sigA(gf) * cB + sigA(gi) * tanhA(gg);
            hbuf[nxt][bB * LSTM_H + u] = sigA(go) * tanhA(cB);
        }
        __syncthreads();
    }

    // ---- output Linear (final h in hbuf[0]: t=511 -> nxt=0) ----
    {
        const int bl = tid / 10, k = tid - bl * 10;   // 16 x 10 = 160
        float sum = b_out[k];
        #pragma unroll
        for (int j = 0; j < LSTM_H; j++)
            sum = fmaf(hbuf[0][bl * LSTM_H + j], w_out[k * LSTM_H + j], sum);
        out[(long)(b0 + bl) * 10 + k] = sum;
    }
}

extern "C" void kernel_launch(void* const* d_in, const int* in_sizes, int n_in,
                              void* d_out, int out_size)
{
    const float* x     = (const float*)d_in[0];
    const float* w_ih  = (const float*)d_in[1];
    const float* w_hh  = (const float*)d_in[2];
    const float* b_ih  = (const float*)d_in[3];
    const float* b_hh  = (const float*)d_in[4];
    const float* w_out = (const float*)d_in[5];
    const float* b_out = (const float*)d_in[6];
    float* out = (float*)d_out;

    lstm_kernel<<<GRID, THREADS>>>(x, w_ih, w_hh, b_ih, b_hh, w_out, b_out, out);
}